// round 2
// baseline (speedup 1.0000x reference)
#include <cuda_runtime.h>
#include <math.h>

#define BB 512
#define LL 196
#define CC 64
#define C2 128
#define CHN 128
#define NEC 512
#define NXC 15

// ---- output layout (flattened tuple order) ----
// rec_feature [B,CH,14,14] | pred [B,1,14,14] | loss | feature_loss | latent_loss | quant_stack [4,B,L,2C]
#define REC_N    (BB*CHN*LL)
#define PRED_OFF (REC_N)
#define LOSS_OFF (REC_N + BB*LL)
#define Q_OFF    (LOSS_OFF + 3)

// ---- scratch (static device memory: allocation-free) ----
__device__ float  g_q4[BB*LL*CC];
__device__ float  g_E5T[NXC*NEC*CC];          // transposed embed5  [cb][n][d]
__device__ float  g_EHT[4*NXC*NEC*C2];        // transposed embed_hi [lev][cb][n][d]
__device__ float  g_e2_5[NXC*NEC];
__device__ float  g_e2_h[4*NXC*NEC];
__device__ double g_acc[6];

__global__ void zero_acc_k() {
    if (threadIdx.x < 6) g_acc[threadIdx.x] = 0.0;
}

// generic [D][N] -> [N][D] transpose per codebook; which: 0 -> g_E5T, 1 -> g_EHT
__global__ void transpose_k(const float* __restrict__ src, int D, int N, int which) {
    __shared__ float tile[32][33];
    float* dstbase = which ? g_EHT : g_E5T;
    const float* s = src + (size_t)blockIdx.z * D * N;
    float* d = dstbase + (size_t)blockIdx.z * D * N;
    int n0 = blockIdx.x * 32, d0 = blockIdx.y * 32;
    for (int ty = threadIdx.y; ty < 32; ty += 8)
        tile[ty][threadIdx.x] = s[(size_t)(d0 + ty) * N + n0 + threadIdx.x];
    __syncthreads();
    for (int ty = threadIdx.y; ty < 32; ty += 8)
        d[(size_t)(n0 + ty) * D + d0 + threadIdx.x] = tile[threadIdx.x][ty];
}

// e2[n] = sum_d E[n][d]^2 — XLA column-reduce style:
// lane-strided unfused partials (d = lane, lane+32, ...), shfl-down tree 16..1
__global__ void e2_k(int D, int total, int which) {
    int warps_per_blk = blockDim.x >> 5;
    int n = blockIdx.x * warps_per_blk + (threadIdx.x >> 5);
    int lane = threadIdx.x & 31;
    if (n >= total) return;
    const float* ET = which ? g_EHT : g_E5T;
    const float* row = ET + (size_t)n * D;
    float p = 0.f;
    for (int j = lane; j < D; j += 32)
        p = __fadd_rn(p, __fmul_rn(row[j], row[j]));
    #pragma unroll
    for (int o = 16; o; o >>= 1)
        p = __fadd_rn(p, __shfl_down_sync(0xffffffffu, p, o));
    if (lane == 0) (which ? g_e2_h : g_e2_5)[n] = p;
}

__device__ __forceinline__ float block_reduce224(float v, float* red) {
    #pragma unroll
    for (int o = 16; o; o >>= 1) v += __shfl_down_sync(0xffffffffu, v, o);
    int w = threadIdx.x >> 5;
    if ((threadIdx.x & 31) == 0) red[w] = v;
    __syncthreads();
    float s = 0.f;
    if (threadIdx.x == 0) {
        #pragma unroll
        for (int i = 0; i < 7; ++i) s += red[i];
    }
    return s;
}

// ---- VQ kernel: one block per (b [, level]); thread t owns row l=t ----
template<int KD, bool HI>
__global__ __launch_bounds__(224, 1)
void vq_kernel(const float* __restrict__ enc,
               const float* __restrict__ Ebase,
               const int*   __restrict__ label,
               float*       __restrict__ qout_hi)
{
    constexpr int PL = 197;  // odd pitch -> conflict-free column access
    extern __shared__ float sm[];
    float* Xst = sm;                         // KD * PL
    float* x2s = Xst + KD * PL;              // 196
    float* Es  = x2s + 196;                  // KD * 64
    float* e2s = Es + KD * 64;               // 64
    int*   bestn = (int*)(e2s + 64);         // 196
    float* red = (float*)(bestn + 196);      // 7

    const int b = blockIdx.x;
    const int lev = HI ? blockIdx.y : 0;
    const int cb = label[b];
    const int tid = threadIdx.x;

    const float* X  = HI ? (enc + (size_t)(3 - lev) * (BB * LL * CC)) : enc;
    const float* Eg = Ebase + ((size_t)(HI ? lev * NXC : 0) + cb) * ((size_t)KD * NEC);
    const float* ET = (HI ? g_EHT : g_E5T) + ((size_t)(HI ? lev * NXC : 0) + cb) * ((size_t)NEC * KD);
    const float* e2 = (HI ? g_e2_h : g_e2_5) + ((size_t)(HI ? lev * NXC : 0) + cb) * NEC;
    float* qout = HI ? (qout_hi + (size_t)lev * (BB * LL * C2)) : g_q4;
    double* acc = g_acc + (HI ? 1 + lev : 0);

    // load X transposed into smem: Xst[d][l]
    for (int idx = tid; idx < LL * KD; idx += 224) {
        int l = idx / KD, d = idx % KD;
        float v;
        if (HI) v = (d < CC) ? X[((size_t)b * LL + l) * CC + d]
                             : g_q4[((size_t)b * LL + l) * CC + (d - CC)];
        else    v = X[((size_t)b * LL + l) * CC + d];
        Xst[d * PL + l] = v;
    }
    __syncthreads();

    // x2 per row — XLA row-reduce style: lane-strided unfused + shfl tree
    {
        const int warp = tid >> 5, lane = tid & 31;
        for (int r = warp; r < LL; r += 7) {
            float p = 0.f;
            #pragma unroll
            for (int j = 0; j < KD / 32; ++j) {
                float xv = Xst[(lane + 32 * j) * PL + r];
                p = __fadd_rn(p, __fmul_rn(xv, xv));
            }
            #pragma unroll
            for (int o = 16; o; o >>= 1)
                p = __fadd_rn(p, __shfl_down_sync(0xffffffffu, p, o));
            if (lane == 0) x2s[r] = p;
        }
    }
    __syncthreads();

    const int l = tid;
    const float x2 = (l < LL) ? x2s[l] : 0.f;

    float best = 3.402823466e38f;
    int bi = 0;
    for (int t = 0; t < NEC / 64; ++t) {
        __syncthreads();
        // load E tile [KD][64] (n-contiguous rows -> coalesced float4)
        for (int i = tid; i < KD * 16; i += 224) {
            int k = i >> 4, j = i & 15;
            ((float4*)Es)[k * 16 + j] = *(const float4*)(Eg + (size_t)k * NEC + t * 64 + j * 4);
        }
        if (tid < 64) e2s[tid] = e2[t * 64 + tid];
        __syncthreads();

        if (l < LL) {
            float a[64];
            #pragma unroll
            for (int j = 0; j < 64; ++j) a[j] = 0.f;
            #pragma unroll 2
            for (int k = 0; k < KD; ++k) {
                float xv = Xst[k * PL + l];
                const float4* er = (const float4*)(Es + k * 64);
                #pragma unroll
                for (int j = 0; j < 16; ++j) {
                    float4 e = er[j];
                    a[4*j+0] = __fmaf_rn(xv, e.x, a[4*j+0]);
                    a[4*j+1] = __fmaf_rn(xv, e.y, a[4*j+1]);
                    a[4*j+2] = __fmaf_rn(xv, e.z, a[4*j+2]);
                    a[4*j+3] = __fmaf_rn(xv, e.w, a[4*j+3]);
                }
            }
            #pragma unroll
            for (int j = 0; j < 64; ++j) {
                // dist = (x2 - 2*xe) + e2 ; strict < keeps first (= argmax(-dist) semantics)
                float dd = __fadd_rn(__fsub_rn(x2, __fmul_rn(2.f, a[j])), e2s[j]);
                if (dd < best) { best = dd; bi = t * 64 + j; }
            }
        }
    }
    if (l < LL) bestn[l] = bi;
    __syncthreads();

    // gather code rows (coalesced from transposed codebook), straight-through q, diff
    float lsum = 0.f;
    for (int idx = tid; idx < LL * KD; idx += 224) {
        int ll = idx / KD, d = idx % KD;
        float c  = ET[(size_t)bestn[ll] * KD + d];
        float xv = Xst[d * PL + ll];
        float df = __fsub_rn(c, xv);
        lsum = __fmaf_rn(df, df, lsum);
        qout[((size_t)b * LL + ll) * KD + d] = __fadd_rn(xv, df);  // q = x + (c - x)
    }
    float bs = block_reduce224(lsum, red);
    if (tid == 0) atomicAdd(acc, (double)bs);
}

// ---- projection + pred + feature loss: one block per b ----
__global__ __launch_bounds__(224, 1)
void proj_kernel(const float* __restrict__ dec,
                 const float* __restrict__ org,
                 const float* __restrict__ W,
                 const float* __restrict__ bvec,
                 const int*   __restrict__ label,
                 float*       __restrict__ rec_out,
                 float*       __restrict__ pred_out)
{
    constexpr int PL = 197;
    extern __shared__ float sm[];
    float* Dst = sm;               // 128*PL
    float* Ws  = Dst + 128 * PL;   // 128*64
    float* red = Ws + 128 * 64;    // 7

    const int b = blockIdx.x, tid = threadIdx.x;
    const int cb = label[b];

    for (int idx = tid; idx < LL * CHN; idx += 224) {
        int l = idx >> 7, d = idx & 127;
        Dst[d * PL + l] = dec[((size_t)l * BB + b) * CHN + d];
    }
    const float* Wcb = W + (size_t)cb * CHN * CHN;
    const float* bcb = bvec + cb * CHN;
    const int l = tid;
    float psum = 0.f;

    for (int t = 0; t < 2; ++t) {
        __syncthreads();
        for (int i = tid; i < 128 * 16; i += 224) {
            int k = i >> 4, j = i & 15;
            ((float4*)Ws)[k * 16 + j] = *(const float4*)(Wcb + (size_t)k * CHN + t * 64 + j * 4);
        }
        __syncthreads();
        if (l < LL) {
            float a[64];
            #pragma unroll
            for (int j = 0; j < 64; ++j) a[j] = 0.f;
            #pragma unroll 2
            for (int k = 0; k < 128; ++k) {
                float xv = Dst[k * PL + l];
                const float4* er = (const float4*)(Ws + k * 64);
                #pragma unroll
                for (int j = 0; j < 16; ++j) {
                    float4 e = er[j];
                    a[4*j+0] = __fmaf_rn(xv, e.x, a[4*j+0]);
                    a[4*j+1] = __fmaf_rn(xv, e.y, a[4*j+1]);
                    a[4*j+2] = __fmaf_rn(xv, e.z, a[4*j+2]);
                    a[4*j+3] = __fmaf_rn(xv, e.w, a[4*j+3]);
                }
            }
            #pragma unroll
            for (int j = 0; j < 64; ++j) {
                int o = t * 64 + j;
                float r = __fadd_rn(a[j], bcb[o]);
                float g = org[(size_t)b * CHN * LL + (size_t)o * LL + l];
                float e = __fsub_rn(r, g);
                psum = __fmaf_rn(e, e, psum);
                rec_out[(size_t)b * CHN * LL + (size_t)o * LL + l] = r;
            }
        }
    }
    if (l < LL) pred_out[(size_t)b * LL + l] = __fsqrt_rn(psum);
    __syncthreads();
    float bs = block_reduce224(psum, red);
    if (tid == 0) atomicAdd(&g_acc[5], (double)bs);
}

__global__ void final_k(float* __restrict__ out) {
    if (threadIdx.x == 0 && blockIdx.x == 0) {
        double latent = g_acc[0] / ((double)BB * LL * CC)
                      + (g_acc[1] + g_acc[2] + g_acc[3] + g_acc[4]) / ((double)BB * LL * C2);
        double feat = g_acc[5] / ((double)BB * CHN * LL);
        out[LOSS_OFF + 0] = (float)(0.25 * latent + feat);
        out[LOSS_OFF + 1] = (float)feat;
        out[LOSS_OFF + 2] = (float)latent;
    }
}

extern "C" void kernel_launch(void* const* d_in, const int* in_sizes, int n_in,
                              void* d_out, int out_size) {
    const float* enc      = (const float*)d_in[0];  // [5,512,196,64]
    const float* dec      = (const float*)d_in[1];  // [196,512,128]
    const float* org      = (const float*)d_in[2];  // [512,128,14,14]
    const float* embed5   = (const float*)d_in[3];  // [15,64,512]
    const float* embed_hi = (const float*)d_in[4];  // [4,15,128,512]
    const float* W        = (const float*)d_in[5];  // [15,128,128]
    const float* bvec     = (const float*)d_in[6];  // [15,128]
    const int*   label    = (const int*)d_in[7];    // [512] int32
    float* out = (float*)d_out;

    const size_t sm64  = (size_t)(64  * 197 + 196 + 64  * 64 + 64) * 4 + 196 * 4 + 32;
    const size_t sm128 = (size_t)(128 * 197 + 196 + 128 * 64 + 64) * 4 + 196 * 4 + 32;
    const size_t smP   = (size_t)(128 * 197 + 128 * 64) * 4 + 32;

    cudaFuncSetAttribute(vq_kernel<64, false>, cudaFuncAttributeMaxDynamicSharedMemorySize, (int)sm64);
    cudaFuncSetAttribute(vq_kernel<128, true>, cudaFuncAttributeMaxDynamicSharedMemorySize, (int)sm128);
    cudaFuncSetAttribute(proj_kernel, cudaFuncAttributeMaxDynamicSharedMemorySize, (int)smP);

    zero_acc_k<<<1, 32>>>();

    transpose_k<<<dim3(16, 2, 15), dim3(32, 8)>>>(embed5,   64,  512, 0);
    transpose_k<<<dim3(16, 4, 60), dim3(32, 8)>>>(embed_hi, 128, 512, 1);
    e2_k<<<(15 * 512 + 7) / 8, 256>>>(64,  15 * 512, 0);
    e2_k<<<(60 * 512 + 7) / 8, 256>>>(128, 60 * 512, 1);

    vq_kernel<64, false><<<512, 224, sm64>>>(enc + (size_t)4 * BB * LL * CC, embed5, label, nullptr);
    vq_kernel<128, true><<<dim3(512, 4), 224, sm128>>>(enc, embed_hi, label, out + Q_OFF);

    proj_kernel<<<512, 224, smP>>>(dec, org, W, bvec, label, out, out + PRED_OFF);

    final_k<<<1, 1>>>(out);
}

// round 4
// speedup vs baseline: 1.2115x; 1.2115x over previous
#include <cuda_runtime.h>
#include <math.h>

#define BB 512
#define LL 196
#define CC 64
#define C2 128
#define CHN 128
#define NEC 512
#define NXC 15

// ---- output layout (flattened tuple order) ----
#define REC_N    (BB*CHN*LL)
#define PRED_OFF (REC_N)
#define LOSS_OFF (REC_N + BB*LL)
#define Q_OFF    (LOSS_OFF + 3)

#define NTHR 416   // 13 warps

// ---- scratch ----
__device__ float  g_q4[BB*LL*CC];
__device__ float  g_E5T[NXC*NEC*CC];
__device__ float  g_EHT[4*NXC*NEC*C2];
__device__ float  g_e2_5[NXC*NEC];
__device__ float  g_e2_h[4*NXC*NEC];
__device__ double g_acc[6];

// packed f32x2 fma: bit-identical to two scalar __fmaf_rn
__device__ __forceinline__ void ffma2(unsigned long long& acc,
                                      unsigned long long a,
                                      unsigned long long b) {
    asm("fma.rn.f32x2 %0, %1, %2, %0;" : "+l"(acc) : "l"(a), "l"(b));
}
__device__ __forceinline__ unsigned long long pack2(float x) {
    unsigned long long r;
    asm("mov.b64 %0, {%1, %1};" : "=l"(r) : "r"(__float_as_uint(x)));
    return r;
}

// [D][N] -> [N][D] transpose per codebook; which 0 -> g_E5T, 1 -> g_EHT
// (also zeroes g_acc from its first block — removes a separate launch)
__global__ void transpose_k(const float* __restrict__ src, int D, int N, int which) {
    __shared__ float tile[32][33];
    if (which == 0 && blockIdx.x == 0 && blockIdx.y == 0 && blockIdx.z == 0 &&
        threadIdx.y == 0 && threadIdx.x < 6)
        g_acc[threadIdx.x] = 0.0;
    float* dstbase = which ? g_EHT : g_E5T;
    const float* s = src + (size_t)blockIdx.z * D * N;
    float* d = dstbase + (size_t)blockIdx.z * D * N;
    int n0 = blockIdx.x * 32, d0 = blockIdx.y * 32;
    for (int ty = threadIdx.y; ty < 32; ty += 8)
        tile[ty][threadIdx.x] = s[(size_t)(d0 + ty) * N + n0 + threadIdx.x];
    __syncthreads();
    for (int ty = threadIdx.y; ty < 32; ty += 8)
        d[(size_t)(n0 + ty) * D + d0 + threadIdx.x] = tile[threadIdx.x][ty];
}

// e2[n] = sum_d E[n][d]^2 — XLA column-reduce style (lane-strided unfused + shfl tree)
__global__ void e2_k(int D, int total, int which) {
    int n = blockIdx.x * (blockDim.x >> 5) + (threadIdx.x >> 5);
    int lane = threadIdx.x & 31;
    if (n >= total) return;
    const float* row = (which ? g_EHT : g_E5T) + (size_t)n * D;
    float p = 0.f;
    for (int j = lane; j < D; j += 32)
        p = __fadd_rn(p, __fmul_rn(row[j], row[j]));
    #pragma unroll
    for (int o = 16; o; o >>= 1)
        p = __fadd_rn(p, __shfl_down_sync(0xffffffffu, p, o));
    if (lane == 0) (which ? g_e2_h : g_e2_5)[n] = p;
}

__device__ __forceinline__ float block_reduce13(float v, float* red) {
    #pragma unroll
    for (int o = 16; o; o >>= 1) v += __shfl_down_sync(0xffffffffu, v, o);
    int w = threadIdx.x >> 5;
    if ((threadIdx.x & 31) == 0) red[w] = v;
    __syncthreads();
    float s = 0.f;
    if (threadIdx.x == 0) {
        #pragma unroll
        for (int i = 0; i < 13; ++i) s += red[i];
    }
    return s;
}

// ---- VQ: one block per (b [, level]); 416 threads = 2 N-halves x 208 row slots ----
template<int KD, bool HI>
__global__ __launch_bounds__(NTHR, 1)
void vq_kernel(const float* __restrict__ enc,
               const float* __restrict__ Ebase,
               const int*   __restrict__ label,
               float*       __restrict__ qout_hi)
{
    constexpr int PL = 197;
    extern __shared__ float sm[];
    float* Xst = sm;                          // KD*PL
    float* x2s = Xst + KD * PL;               // 196
    float* Es  = x2s + 196;                   // KD*64 (offset multiple of 4 floats)
    float* e2s = Es + KD * 64;                // 64
    float* bv  = e2s + 64;                    // 416
    int*   bn  = (int*)(bv + NTHR);           // 416
    int*   bestn = bn + NTHR;                 // 196
    float* red = (float*)(bestn + 196);       // 13

    const int b = blockIdx.x;
    const int lev = HI ? blockIdx.y : 0;
    const int cb = label[b];
    const int tid = threadIdx.x;
    const int half = (tid >= 208) ? 1 : 0;
    const int l = tid - 208 * half;

    const float* X  = HI ? (enc + (size_t)(3 - lev) * (BB * LL * CC)) : enc;
    const float* Eg = Ebase + ((size_t)(HI ? lev * NXC : 0) + cb) * ((size_t)KD * NEC);
    const float* ET = (HI ? g_EHT : g_E5T) + ((size_t)(HI ? lev * NXC : 0) + cb) * ((size_t)NEC * KD);
    const float* e2 = (HI ? g_e2_h : g_e2_5) + ((size_t)(HI ? lev * NXC : 0) + cb) * NEC;
    float* qout = HI ? (qout_hi + (size_t)lev * (BB * LL * C2)) : g_q4;
    double* acc = g_acc + (HI ? 1 + lev : 0);

    // stage X transposed: Xst[d][l]
    for (int idx = tid; idx < LL * KD; idx += NTHR) {
        int ll = idx / KD, d = idx % KD;
        float v;
        if (HI) v = (d < CC) ? X[((size_t)b * LL + ll) * CC + d]
                             : g_q4[((size_t)b * LL + ll) * CC + (d - CC)];
        else    v = X[((size_t)b * LL + ll) * CC + d];
        Xst[d * PL + ll] = v;
    }
    __syncthreads();

    // x2 per row — XLA row-reduce (lane-strided unfused + shfl tree)
    {
        const int warp = tid >> 5, lane = tid & 31;
        for (int r = warp; r < LL; r += 13) {
            float p = 0.f;
            #pragma unroll
            for (int j = 0; j < KD / 32; ++j) {
                float xv = Xst[(lane + 32 * j) * PL + r];
                p = __fadd_rn(p, __fmul_rn(xv, xv));
            }
            #pragma unroll
            for (int o = 16; o; o >>= 1)
                p = __fadd_rn(p, __shfl_down_sync(0xffffffffu, p, o));
            if (lane == 0) x2s[r] = p;
        }
    }
    __syncthreads();

    const float x2 = (l < LL) ? x2s[l] : 0.f;
    float best = 3.402823466e38f;
    int bi = 0;

    for (int t = 0; t < NEC / 64; ++t) {
        __syncthreads();
        for (int i = tid; i < KD * 16; i += NTHR) {
            int k = i >> 4, j = i & 15;
            ((float4*)Es)[k * 16 + j] = *(const float4*)(Eg + (size_t)k * NEC + t * 64 + j * 4);
        }
        if (tid < 64) e2s[tid] = e2[t * 64 + tid];
        __syncthreads();

        if (l < LL) {
            unsigned long long a2[16];
            #pragma unroll
            for (int j = 0; j < 16; ++j) a2[j] = 0ull;
            #pragma unroll 2
            for (int k = 0; k < KD; ++k) {
                unsigned long long xx = pack2(Xst[k * PL + l]);
                const ulonglong2* er = (const ulonglong2*)(Es + k * 64 + half * 32);
                #pragma unroll
                for (int j = 0; j < 8; ++j) {
                    ulonglong2 e = er[j];
                    ffma2(a2[2 * j], xx, e.x);
                    ffma2(a2[2 * j + 1], xx, e.y);
                }
            }
            #pragma unroll
            for (int j = 0; j < 16; ++j) {
                float alo = __uint_as_float((unsigned)a2[j]);
                float ahi = __uint_as_float((unsigned)(a2[j] >> 32));
                int nloc = half * 32 + 2 * j;
                float d0 = __fadd_rn(__fsub_rn(x2, __fmul_rn(2.f, alo)), e2s[nloc]);
                float d1 = __fadd_rn(__fsub_rn(x2, __fmul_rn(2.f, ahi)), e2s[nloc + 1]);
                if (d0 < best) { best = d0; bi = t * 64 + nloc; }
                if (d1 < best) { best = d1; bi = t * 64 + nloc + 1; }
            }
        }
    }
    bv[tid] = best; bn[tid] = bi;
    __syncthreads();
    // combine halves: global first-min (lowest index among equal minima)
    if (tid < 208 && l < LL) {
        float v0 = bv[tid], v1 = bv[tid + 208];
        int n0 = bn[tid], n1 = bn[tid + 208];
        bestn[l] = (v1 < v0 || (v1 == v0 && n1 < n0)) ? n1 : n0;
    }
    __syncthreads();

    // gather codes, straight-through q, diff
    float lsum = 0.f;
    for (int idx = tid; idx < LL * KD; idx += NTHR) {
        int ll = idx / KD, d = idx % KD;
        float c  = ET[(size_t)bestn[ll] * KD + d];
        float xv = Xst[d * PL + ll];
        float df = __fsub_rn(c, xv);
        lsum = __fmaf_rn(df, df, lsum);
        qout[((size_t)b * LL + ll) * KD + d] = __fadd_rn(xv, df);
    }
    float bs = block_reduce13(lsum, red);
    if (tid == 0) atomicAdd(acc, (double)bs);
}

// ---- projection + pred + feature loss ----
__global__ __launch_bounds__(NTHR, 1)
void proj_kernel(const float* __restrict__ dec,
                 const float* __restrict__ org,
                 const float* __restrict__ W,
                 const float* __restrict__ bvec,
                 const int*   __restrict__ label,
                 float*       __restrict__ rec_out,
                 float*       __restrict__ pred_out)
{
    constexpr int PL = 197;
    extern __shared__ float sm[];
    float* Dst = sm;                // 128*PL
    float* ps  = Dst + 128 * PL;    // 208
    float* Ws  = ps + 208;          // 128*64 (offset multiple of 4 floats)
    float* red = Ws + 128 * 64;     // 13

    const int b = blockIdx.x, tid = threadIdx.x;
    const int cb = label[b];
    const int half = (tid >= 208) ? 1 : 0;
    const int l = tid - 208 * half;

    for (int idx = tid; idx < LL * CHN; idx += NTHR) {
        int ll = idx >> 7, d = idx & 127;
        Dst[d * PL + ll] = dec[((size_t)ll * BB + b) * CHN + d];
    }
    const float* Wcb = W + (size_t)cb * CHN * CHN;
    const float* bcb = bvec + cb * CHN;
    float psum = 0.f;

    for (int t = 0; t < 2; ++t) {
        __syncthreads();
        for (int i = tid; i < 128 * 16; i += NTHR) {
            int k = i >> 4, j = i & 15;
            ((float4*)Ws)[k * 16 + j] = *(const float4*)(Wcb + (size_t)k * CHN + t * 64 + j * 4);
        }
        __syncthreads();
        if (l < LL) {
            unsigned long long a2[16];
            #pragma unroll
            for (int j = 0; j < 16; ++j) a2[j] = 0ull;
            #pragma unroll 2
            for (int k = 0; k < 128; ++k) {
                unsigned long long xx = pack2(Dst[k * PL + l]);
                const ulonglong2* er = (const ulonglong2*)(Ws + k * 64 + half * 32);
                #pragma unroll
                for (int j = 0; j < 8; ++j) {
                    ulonglong2 e = er[j];
                    ffma2(a2[2 * j], xx, e.x);
                    ffma2(a2[2 * j + 1], xx, e.y);
                }
            }
            #pragma unroll
            for (int j = 0; j < 16; ++j) {
                #pragma unroll
                for (int s = 0; s < 2; ++s) {
                    float av = __uint_as_float((unsigned)(a2[j] >> (32 * s)));
                    int o = t * 64 + half * 32 + 2 * j + s;
                    float r = __fadd_rn(av, bcb[o]);
                    float g = org[(size_t)b * CHN * LL + (size_t)o * LL + l];
                    float e = __fsub_rn(r, g);
                    psum = __fmaf_rn(e, e, psum);
                    rec_out[(size_t)b * CHN * LL + (size_t)o * LL + l] = r;
                }
            }
        }
    }
    __syncthreads();
    if (half == 1 && l < LL) ps[l] = psum;
    __syncthreads();
    if (half == 0 && l < LL)
        pred_out[(size_t)b * LL + l] = __fsqrt_rn(__fadd_rn(psum, ps[l]));
    float bs = block_reduce13(psum, red);
    if (tid == 0) atomicAdd(&g_acc[5], (double)bs);
}

__global__ void final_k(float* __restrict__ out) {
    if (threadIdx.x == 0 && blockIdx.x == 0) {
        double latent = g_acc[0] / ((double)BB * LL * CC)
                      + (g_acc[1] + g_acc[2] + g_acc[3] + g_acc[4]) / ((double)BB * LL * C2);
        double feat = g_acc[5] / ((double)BB * CHN * LL);
        out[LOSS_OFF + 0] = (float)(0.25 * latent + feat);
        out[LOSS_OFF + 1] = (float)feat;
        out[LOSS_OFF + 2] = (float)latent;
    }
}

extern "C" void kernel_launch(void* const* d_in, const int* in_sizes, int n_in,
                              void* d_out, int out_size) {
    const float* enc      = (const float*)d_in[0];
    const float* dec      = (const float*)d_in[1];
    const float* org      = (const float*)d_in[2];
    const float* embed5   = (const float*)d_in[3];
    const float* embed_hi = (const float*)d_in[4];
    const float* W        = (const float*)d_in[5];
    const float* bvec     = (const float*)d_in[6];
    const int*   label    = (const int*)d_in[7];
    float* out = (float*)d_out;

    const size_t sm64  = (size_t)(64  * 197 + 196 + 64  * 64 + 64 + NTHR) * 4
                       + (NTHR + 196) * 4 + 13 * 4 + 32;
    const size_t sm128 = (size_t)(128 * 197 + 196 + 128 * 64 + 64 + NTHR) * 4
                       + (NTHR + 196) * 4 + 13 * 4 + 32;
    const size_t smP   = (size_t)(128 * 197 + 208 + 128 * 64 + 13) * 4 + 32;

    cudaFuncSetAttribute(vq_kernel<64, false>, cudaFuncAttributeMaxDynamicSharedMemorySize, (int)sm64);
    cudaFuncSetAttribute(vq_kernel<128, true>, cudaFuncAttributeMaxDynamicSharedMemorySize, (int)sm128);
    cudaFuncSetAttribute(proj_kernel, cudaFuncAttributeMaxDynamicSharedMemorySize, (int)smP);

    transpose_k<<<dim3(16, 2, 15), dim3(32, 8)>>>(embed5,   64,  512, 0);   // also zeroes g_acc
    transpose_k<<<dim3(16, 4, 60), dim3(32, 8)>>>(embed_hi, 128, 512, 1);
    e2_k<<<(15 * 512 + 7) / 8, 256>>>(64,  15 * 512, 0);
    e2_k<<<(60 * 512 + 7) / 8, 256>>>(128, 60 * 512, 1);

    vq_kernel<64, false><<<512, NTHR, sm64>>>(enc + (size_t)4 * BB * LL * CC, embed5, label, nullptr);
    vq_kernel<128, true><<<dim3(512, 4), NTHR, sm128>>>(enc, embed_hi, label, out + Q_OFF);

    proj_kernel<<<512, NTHR, smP>>>(dec, org, W, bvec, label, out, out + PRED_OFF);

    final_k<<<1, 1>>>(out);
}

// round 5
// speedup vs baseline: 1.3400x; 1.1060x over previous
#include <cuda_runtime.h>
#include <math.h>

#define BB 512
#define LL 196
#define CC 64
#define C2 128
#define CHN 128
#define NEC 512
#define NXC 15

// ---- output layout (flattened tuple order) ----
#define REC_N    (BB*CHN*LL)
#define PRED_OFF (REC_N)
#define LOSS_OFF (REC_N + BB*LL)
#define Q_OFF    (LOSS_OFF + 3)

#define NTHR 416        // 13 warps
#define ROWS 98         // rows per VQ block (196 = 2 x 98)
#define QSLOT 104       // thread slots per quarter (4*104 = 416)

// ---- scratch ----
__device__ float  g_q4[BB*LL*CC];
__device__ float  g_E5T[NXC*NEC*CC];
__device__ float  g_EHT[4*NXC*NEC*C2];
__device__ float  g_e2_5[NXC*NEC];
__device__ float  g_e2_h[4*NXC*NEC];
__device__ double g_acc[6];

// packed f32x2 fma: bit-identical to two scalar __fmaf_rn
__device__ __forceinline__ void ffma2(unsigned long long& acc,
                                      unsigned long long a,
                                      unsigned long long b) {
    asm("fma.rn.f32x2 %0, %1, %2, %0;" : "+l"(acc) : "l"(a), "l"(b));
}
__device__ __forceinline__ unsigned long long pack2(float x) {
    unsigned long long r;
    asm("mov.b64 %0, {%1, %1};" : "=l"(r) : "r"(__float_as_uint(x)));
    return r;
}

// [D][N] -> [N][D] transpose per codebook; which 0 -> g_E5T, 1 -> g_EHT
// (also zeroes g_acc from its first block)
__global__ void transpose_k(const float* __restrict__ src, int D, int N, int which) {
    __shared__ float tile[32][33];
    if (which == 0 && blockIdx.x == 0 && blockIdx.y == 0 && blockIdx.z == 0 &&
        threadIdx.y == 0 && threadIdx.x < 6)
        g_acc[threadIdx.x] = 0.0;
    float* dstbase = which ? g_EHT : g_E5T;
    const float* s = src + (size_t)blockIdx.z * D * N;
    float* d = dstbase + (size_t)blockIdx.z * D * N;
    int n0 = blockIdx.x * 32, d0 = blockIdx.y * 32;
    for (int ty = threadIdx.y; ty < 32; ty += 8)
        tile[ty][threadIdx.x] = s[(size_t)(d0 + ty) * N + n0 + threadIdx.x];
    __syncthreads();
    for (int ty = threadIdx.y; ty < 32; ty += 8)
        d[(size_t)(n0 + ty) * D + d0 + threadIdx.x] = tile[threadIdx.x][ty];
}

// e2 for BOTH tables in one launch (keeps launch count down so the profiled
// slot lands on vq_kernel<64>). XLA column-reduce style:
// lane-strided unfused partials + shfl-down tree — bit-identical to before.
__global__ void e2_all_k() {
    int n = blockIdx.x * (blockDim.x >> 5) + (threadIdx.x >> 5);
    int lane = threadIdx.x & 31;
    const int T5 = NXC * NEC;                 // 7680 rows of D=64
    const int TH = 4 * NXC * NEC;             // 30720 rows of D=128
    if (n >= T5 + TH) return;
    const float* row;
    float* dst;
    int D;
    if (n < T5) { row = g_E5T + (size_t)n * CC;        dst = g_e2_5 + n;        D = CC; }
    else        { row = g_EHT + (size_t)(n - T5) * C2; dst = g_e2_h + (n - T5); D = C2; }
    float p = 0.f;
    for (int j = lane; j < D; j += 32)
        p = __fadd_rn(p, __fmul_rn(row[j], row[j]));
    #pragma unroll
    for (int o = 16; o; o >>= 1)
        p = __fadd_rn(p, __shfl_down_sync(0xffffffffu, p, o));
    if (lane == 0) *dst = p;
}

__device__ __forceinline__ float block_reduce13(float v, float* red) {
    #pragma unroll
    for (int o = 16; o; o >>= 1) v += __shfl_down_sync(0xffffffffu, v, o);
    int w = threadIdx.x >> 5;
    if ((threadIdx.x & 31) == 0) red[w] = v;
    __syncthreads();
    float s = 0.f;
    if (threadIdx.x == 0) {
        #pragma unroll
        for (int i = 0; i < 13; ++i) s += red[i];
    }
    return s;
}

// ---- VQ: grid (B, levels, 2); each block handles 98 rows; 416 threads =
// 4 code-quarters (16 codes) x 104 row slots. 2 blocks/SM (88KB smem).
template<int KD, bool HI>
__global__ __launch_bounds__(NTHR, 2)
void vq_kernel(const float* __restrict__ enc,
               const float* __restrict__ Ebase,
               const int*   __restrict__ label,
               float*       __restrict__ qout_hi)
{
    constexpr int PL = 99;                    // 99 mod 32 = 3 -> conflict-free
    constexpr int ESOFF = (KD * PL + ROWS + 3) & ~3;
    extern __shared__ float sm[];
    float* Xst = sm;                          // KD*PL
    float* x2s = Xst + KD * PL;               // 98
    float* Es  = sm + ESOFF;                  // KD*64 (16B aligned)
    float* e2s = Es + KD * 64;                // 64
    float* bv  = e2s + 64;                    // 416
    int*   bn  = (int*)(bv + NTHR);           // 416
    int*   bestn = bn + NTHR;                 // 98
    float* red = (float*)(bestn + ROWS);      // 13

    const int b = blockIdx.x;
    const int lev = HI ? blockIdx.y : 0;
    const int row0 = blockIdx.z * ROWS;
    const int cb = label[b];
    const int tid = threadIdx.x;
    const int qtr = tid / QSLOT;
    const int slot = tid - qtr * QSLOT;
    const bool act = slot < ROWS;

    const float* X  = HI ? (enc + (size_t)(3 - lev) * (BB * LL * CC)) : enc;
    const float* Eg = Ebase + ((size_t)(HI ? lev * NXC : 0) + cb) * ((size_t)KD * NEC);
    const float* ET = (HI ? g_EHT : g_E5T) + ((size_t)(HI ? lev * NXC : 0) + cb) * ((size_t)NEC * KD);
    const float* e2 = (HI ? g_e2_h : g_e2_5) + ((size_t)(HI ? lev * NXC : 0) + cb) * NEC;
    float* qout = HI ? (qout_hi + (size_t)lev * (BB * LL * C2)) : g_q4;
    double* acc = g_acc + (HI ? 1 + lev : 0);

    // stage this block's 98 rows of X, transposed: Xst[d][l]
    for (int idx = tid; idx < ROWS * KD; idx += NTHR) {
        int ll = idx / KD, d = idx % KD;
        int gl = row0 + ll;
        float v;
        if (HI) v = (d < CC) ? X[((size_t)b * LL + gl) * CC + d]
                             : g_q4[((size_t)b * LL + gl) * CC + (d - CC)];
        else    v = X[((size_t)b * LL + gl) * CC + d];
        Xst[d * PL + ll] = v;
    }
    __syncthreads();

    // x2 per row — XLA row-reduce (lane-strided unfused + shfl tree)
    {
        const int warp = tid >> 5, lane = tid & 31;
        for (int r = warp; r < ROWS; r += 13) {
            float p = 0.f;
            #pragma unroll
            for (int j = 0; j < KD / 32; ++j) {
                float xv = Xst[(lane + 32 * j) * PL + r];
                p = __fadd_rn(p, __fmul_rn(xv, xv));
            }
            #pragma unroll
            for (int o = 16; o; o >>= 1)
                p = __fadd_rn(p, __shfl_down_sync(0xffffffffu, p, o));
            if (lane == 0) x2s[r] = p;
        }
    }
    __syncthreads();

    const float x2 = act ? x2s[slot] : 0.f;
    float best = 3.402823466e38f;
    int bi = 0x7fffffff;

    for (int t = 0; t < NEC / 64; ++t) {
        __syncthreads();
        for (int i = tid; i < KD * 16; i += NTHR) {
            int k = i >> 4, j = i & 15;
            ((float4*)Es)[k * 16 + j] = *(const float4*)(Eg + (size_t)k * NEC + t * 64 + j * 4);
        }
        if (tid < 64) e2s[tid] = e2[t * 64 + tid];
        __syncthreads();

        if (act) {
            unsigned long long a2[8];
            #pragma unroll
            for (int m = 0; m < 8; ++m) a2[m] = 0ull;
            #pragma unroll 2
            for (int k = 0; k < KD; ++k) {
                unsigned long long xx = pack2(Xst[k * PL + slot]);
                const ulonglong2* er = (const ulonglong2*)(Es + k * 64 + qtr * 16);
                #pragma unroll
                for (int j = 0; j < 4; ++j) {
                    ulonglong2 e = er[j];
                    ffma2(a2[2 * j],     xx, e.x);
                    ffma2(a2[2 * j + 1], xx, e.y);
                }
            }
            #pragma unroll
            for (int m = 0; m < 8; ++m) {
                float alo = __uint_as_float((unsigned)a2[m]);
                float ahi = __uint_as_float((unsigned)(a2[m] >> 32));
                int n0 = t * 64 + qtr * 16 + 2 * m;
                float d0 = __fadd_rn(__fsub_rn(x2, __fmul_rn(2.f, alo)), e2s[qtr * 16 + 2 * m]);
                float d1 = __fadd_rn(__fsub_rn(x2, __fmul_rn(2.f, ahi)), e2s[qtr * 16 + 2 * m + 1]);
                if (d0 < best) { best = d0; bi = n0; }
                if (d1 < best) { best = d1; bi = n0 + 1; }
            }
        }
    }
    bv[tid] = best; bn[tid] = bi;
    __syncthreads();
    // combine 4 quarters: global first-min = smallest index among equal minima
    if (tid < ROWS) {
        float v = bv[tid]; int n = bn[tid];
        #pragma unroll
        for (int q = 1; q < 4; ++q) {
            float vq = bv[q * QSLOT + tid]; int nq = bn[q * QSLOT + tid];
            if (vq < v || (vq == v && nq < n)) { v = vq; n = nq; }
        }
        bestn[tid] = n;
    }
    __syncthreads();

    // gather codes, straight-through q, diff (this block's rows only)
    float lsum = 0.f;
    for (int idx = tid; idx < ROWS * KD; idx += NTHR) {
        int ll = idx / KD, d = idx % KD;
        float c  = ET[(size_t)bestn[ll] * KD + d];
        float xv = Xst[d * PL + ll];
        float df = __fsub_rn(c, xv);
        lsum = __fmaf_rn(df, df, lsum);
        qout[((size_t)b * LL + row0 + ll) * KD + d] = __fadd_rn(xv, df);
    }
    float bs = block_reduce13(lsum, red);
    if (tid == 0) atomicAdd(acc, (double)bs);
}

// ---- projection + pred + feature loss (unchanged from passing R4 kernel) ----
__global__ __launch_bounds__(NTHR, 1)
void proj_kernel(const float* __restrict__ dec,
                 const float* __restrict__ org,
                 const float* __restrict__ W,
                 const float* __restrict__ bvec,
                 const int*   __restrict__ label,
                 float*       __restrict__ rec_out,
                 float*       __restrict__ pred_out)
{
    constexpr int PL = 197;
    extern __shared__ float sm[];
    float* Dst = sm;                // 128*PL
    float* ps  = Dst + 128 * PL;    // 208
    float* Ws  = ps + 208;          // 128*64
    float* red = Ws + 128 * 64;     // 13

    const int b = blockIdx.x, tid = threadIdx.x;
    const int cb = label[b];
    const int half = (tid >= 208) ? 1 : 0;
    const int l = tid - 208 * half;

    for (int idx = tid; idx < LL * CHN; idx += NTHR) {
        int ll = idx >> 7, d = idx & 127;
        Dst[d * PL + ll] = dec[((size_t)ll * BB + b) * CHN + d];
    }
    const float* Wcb = W + (size_t)cb * CHN * CHN;
    const float* bcb = bvec + cb * CHN;
    float psum = 0.f;

    for (int t = 0; t < 2; ++t) {
        __syncthreads();
        for (int i = tid; i < 128 * 16; i += NTHR) {
            int k = i >> 4, j = i & 15;
            ((float4*)Ws)[k * 16 + j] = *(const float4*)(Wcb + (size_t)k * CHN + t * 64 + j * 4);
        }
        __syncthreads();
        if (l < LL) {
            unsigned long long a2[16];
            #pragma unroll
            for (int j = 0; j < 16; ++j) a2[j] = 0ull;
            #pragma unroll 2
            for (int k = 0; k < 128; ++k) {
                unsigned long long xx = pack2(Dst[k * PL + l]);
                const ulonglong2* er = (const ulonglong2*)(Ws + k * 64 + half * 32);
                #pragma unroll
                for (int j = 0; j < 8; ++j) {
                    ulonglong2 e = er[j];
                    ffma2(a2[2 * j], xx, e.x);
                    ffma2(a2[2 * j + 1], xx, e.y);
                }
            }
            #pragma unroll
            for (int j = 0; j < 16; ++j) {
                #pragma unroll
                for (int s = 0; s < 2; ++s) {
                    float av = __uint_as_float((unsigned)(a2[j] >> (32 * s)));
                    int o = t * 64 + half * 32 + 2 * j + s;
                    float r = __fadd_rn(av, bcb[o]);
                    float g = org[(size_t)b * CHN * LL + (size_t)o * LL + l];
                    float e = __fsub_rn(r, g);
                    psum = __fmaf_rn(e, e, psum);
                    rec_out[(size_t)b * CHN * LL + (size_t)o * LL + l] = r;
                }
            }
        }
    }
    __syncthreads();
    if (half == 1 && l < LL) ps[l] = psum;
    __syncthreads();
    if (half == 0 && l < LL)
        pred_out[(size_t)b * LL + l] = __fsqrt_rn(__fadd_rn(psum, ps[l]));
    float bs = block_reduce13(psum, red);
    if (tid == 0) atomicAdd(&g_acc[5], (double)bs);
}

__global__ void final_k(float* __restrict__ out) {
    if (threadIdx.x == 0 && blockIdx.x == 0) {
        double latent = g_acc[0] / ((double)BB * LL * CC)
                      + (g_acc[1] + g_acc[2] + g_acc[3] + g_acc[4]) / ((double)BB * LL * C2);
        double feat = g_acc[5] / ((double)BB * CHN * LL);
        out[LOSS_OFF + 0] = (float)(0.25 * latent + feat);
        out[LOSS_OFF + 1] = (float)feat;
        out[LOSS_OFF + 2] = (float)latent;
    }
}

extern "C" void kernel_launch(void* const* d_in, const int* in_sizes, int n_in,
                              void* d_out, int out_size) {
    const float* enc      = (const float*)d_in[0];
    const float* dec      = (const float*)d_in[1];
    const float* org      = (const float*)d_in[2];
    const float* embed5   = (const float*)d_in[3];
    const float* embed_hi = (const float*)d_in[4];
    const float* W        = (const float*)d_in[5];
    const float* bvec     = (const float*)d_in[6];
    const int*   label    = (const int*)d_in[7];
    float* out = (float*)d_out;

    // smem: ESOFF + KD*64 (Es) + 64 (e2s) + 416 (bv) + 416 (bn) + 98 (bestn) + 13 (red) + pad
    const size_t sm64  = (size_t)(((64  * 99 + ROWS + 3) & ~3) + 64  * 64 + 64 + NTHR + NTHR + ROWS + 13 + 16) * 4;
    const size_t sm128 = (size_t)(((128 * 99 + ROWS + 3) & ~3) + 128 * 64 + 64 + NTHR + NTHR + ROWS + 13 + 16) * 4;
    const size_t smP   = (size_t)(128 * 197 + 208 + 128 * 64 + 13 + 16) * 4;

    cudaFuncSetAttribute(vq_kernel<64, false>, cudaFuncAttributeMaxDynamicSharedMemorySize, (int)sm64);
    cudaFuncSetAttribute(vq_kernel<128, true>, cudaFuncAttributeMaxDynamicSharedMemorySize, (int)sm128);
    cudaFuncSetAttribute(proj_kernel, cudaFuncAttributeMaxDynamicSharedMemorySize, (int)smP);

    // launch order matters for the ncu window (profiled slot = 0-based launch 3 = vq5)
    transpose_k<<<dim3(16, 2, 15), dim3(32, 8)>>>(embed5,   64,  512, 0);   // 0 (also zeroes g_acc)
    transpose_k<<<dim3(16, 4, 60), dim3(32, 8)>>>(embed_hi, 128, 512, 1);   // 1
    e2_all_k<<<(75 * 512 + 7) / 8, 256>>>();                                // 2

    vq_kernel<64, false><<<dim3(512, 1, 2), NTHR, sm64>>>(                  // 3 <- profiled
        enc + (size_t)4 * BB * LL * CC, embed5, label, nullptr);
    vq_kernel<128, true><<<dim3(512, 4, 2), NTHR, sm128>>>(                 // 4
        enc, embed_hi, label, out + Q_OFF);

    proj_kernel<<<512, NTHR, smP>>>(dec, org, W, bvec, label, out, out + PRED_OFF);  // 5

    final_k<<<1, 1>>>(out);                                                 // 6
}

// round 6
// speedup vs baseline: 1.4634x; 1.0921x over previous
#include <cuda_runtime.h>
#include <math.h>

#define BB 512
#define LL 196
#define CC 64
#define C2 128
#define CHN 128
#define NEC 512
#define NXC 15

// ---- output layout (flattened tuple order) ----
#define REC_N    (BB*CHN*LL)
#define PRED_OFF (REC_N)
#define LOSS_OFF (REC_N + BB*LL)
#define Q_OFF    (LOSS_OFF + 3)

#define NTHR 416        // 13 warps
#define QSLOT 104       // row slots per code-quarter (4*104 = 416)

// ---- scratch ----
__device__ float  g_q4[BB*LL*CC];
__device__ float  g_E5T[NXC*NEC*CC];
__device__ float  g_EHT[4*NXC*NEC*C2];
__device__ float  g_e2_5[NXC*NEC];
__device__ float  g_e2_h[4*NXC*NEC];
__device__ double g_acc[6];

// packed f32x2 fma: bit-identical to two scalar __fmaf_rn
__device__ __forceinline__ void ffma2(unsigned long long& acc,
                                      unsigned long long a,
                                      unsigned long long b) {
    asm("fma.rn.f32x2 %0, %1, %2, %0;" : "+l"(acc) : "l"(a), "l"(b));
}
__device__ __forceinline__ unsigned long long pack2(float x) {
    unsigned long long r;
    asm("mov.b64 %0, {%1, %1};" : "=l"(r) : "r"(__float_as_uint(x)));
    return r;
}

// [D][N] -> [N][D] transpose per codebook; which 0 -> g_E5T, 1 -> g_EHT
// (also zeroes g_acc from its first block)
__global__ void transpose_k(const float* __restrict__ src, int D, int N, int which) {
    __shared__ float tile[32][33];
    if (which == 0 && blockIdx.x == 0 && blockIdx.y == 0 && blockIdx.z == 0 &&
        threadIdx.y == 0 && threadIdx.x < 6)
        g_acc[threadIdx.x] = 0.0;
    float* dstbase = which ? g_EHT : g_E5T;
    const float* s = src + (size_t)blockIdx.z * D * N;
    float* d = dstbase + (size_t)blockIdx.z * D * N;
    int n0 = blockIdx.x * 32, d0 = blockIdx.y * 32;
    for (int ty = threadIdx.y; ty < 32; ty += 8)
        tile[ty][threadIdx.x] = s[(size_t)(d0 + ty) * N + n0 + threadIdx.x];
    __syncthreads();
    for (int ty = threadIdx.y; ty < 32; ty += 8)
        d[(size_t)(n0 + ty) * D + d0 + threadIdx.x] = tile[threadIdx.x][ty];
}

// e2 for BOTH tables in one launch. XLA column-reduce style:
// lane-strided unfused partials + shfl-down tree — bit-identical to before.
__global__ void e2_all_k() {
    int n = blockIdx.x * (blockDim.x >> 5) + (threadIdx.x >> 5);
    int lane = threadIdx.x & 31;
    const int T5 = NXC * NEC;
    const int TH = 4 * NXC * NEC;
    if (n >= T5 + TH) return;
    const float* row;
    float* dst;
    int D;
    if (n < T5) { row = g_E5T + (size_t)n * CC;        dst = g_e2_5 + n;        D = CC; }
    else        { row = g_EHT + (size_t)(n - T5) * C2; dst = g_e2_h + (n - T5); D = C2; }
    float p = 0.f;
    for (int j = lane; j < D; j += 32)
        p = __fadd_rn(p, __fmul_rn(row[j], row[j]));
    #pragma unroll
    for (int o = 16; o; o >>= 1)
        p = __fadd_rn(p, __shfl_down_sync(0xffffffffu, p, o));
    if (lane == 0) *dst = p;
}

__device__ __forceinline__ float block_reduce13(float v, float* red) {
    #pragma unroll
    for (int o = 16; o; o >>= 1) v += __shfl_down_sync(0xffffffffu, v, o);
    int w = threadIdx.x >> 5;
    if ((threadIdx.x & 31) == 0) red[w] = v;
    __syncthreads();
    float s = 0.f;
    if (threadIdx.x == 0) {
        #pragma unroll
        for (int i = 0; i < 13; ++i) s += red[i];
    }
    return s;
}

// ---- VQ: one block per (b [, level]), full 196 rows; 416 threads =
// 4 code-quarters (16 codes) x 104 row slots, each slot owns rows slot and slot+104.
// Per k: 2 LDS.32 + 4 LDS.128 + 16 FFMA2  (LDS/FFMA2 = 0.375)
template<int KD, bool HI, int MAXB>
__global__ __launch_bounds__(NTHR, MAXB)
void vq_kernel(const float* __restrict__ enc,
               const float* __restrict__ Ebase,
               const int*   __restrict__ label,
               float*       __restrict__ qout_hi)
{
    constexpr int PL = 197;                   // 197 mod 32 = 5 -> conflict-free
    extern __shared__ float sm[];
    float* Xst = sm;                          // KD*PL
    float* x2s = Xst + KD * PL;               // 196
    float* Es  = x2s + 196;                   // KD*64 (offset mult of 4 floats)
    float* e2s = Es + KD * 64;                // 64
    float* bv  = e2s + 64;                    // 2*416 (A section, B section)
    int*   bn  = (int*)(bv + 2 * NTHR);       // 2*416
    int*   bestn = bn + 2 * NTHR;             // 196
    float* red = (float*)(bestn + LL);        // 13

    const int b = blockIdx.x;
    const int lev = HI ? blockIdx.y : 0;
    const int cb = label[b];
    const int tid = threadIdx.x;
    const int qtr = tid / QSLOT;
    const int slot = tid - qtr * QSLOT;       // row A = slot
    const bool hasB = (slot < LL - QSLOT);    // row B = slot + 104 (92 valid)
    const int rowB = hasB ? slot + QSLOT : slot;

    const float* X  = HI ? (enc + (size_t)(3 - lev) * (BB * LL * CC)) : enc;
    const float* Eg = Ebase + ((size_t)(HI ? lev * NXC : 0) + cb) * ((size_t)KD * NEC);
    const float* ET = (HI ? g_EHT : g_E5T) + ((size_t)(HI ? lev * NXC : 0) + cb) * ((size_t)NEC * KD);
    const float* e2 = (HI ? g_e2_h : g_e2_5) + ((size_t)(HI ? lev * NXC : 0) + cb) * NEC;
    float* qout = HI ? (qout_hi + (size_t)lev * (BB * LL * C2)) : g_q4;
    double* acc = g_acc + (HI ? 1 + lev : 0);

    // stage X transposed: Xst[d][l]
    for (int idx = tid; idx < LL * KD; idx += NTHR) {
        int ll = idx / KD, d = idx % KD;
        float v;
        if (HI) v = (d < CC) ? X[((size_t)b * LL + ll) * CC + d]
                             : g_q4[((size_t)b * LL + ll) * CC + (d - CC)];
        else    v = X[((size_t)b * LL + ll) * CC + d];
        Xst[d * PL + ll] = v;
    }
    __syncthreads();

    // x2 per row — XLA row-reduce (lane-strided unfused + shfl tree)
    {
        const int warp = tid >> 5, lane = tid & 31;
        for (int r = warp; r < LL; r += 13) {
            float p = 0.f;
            #pragma unroll
            for (int j = 0; j < KD / 32; ++j) {
                float xv = Xst[(lane + 32 * j) * PL + r];
                p = __fadd_rn(p, __fmul_rn(xv, xv));
            }
            #pragma unroll
            for (int o = 16; o; o >>= 1)
                p = __fadd_rn(p, __shfl_down_sync(0xffffffffu, p, o));
            if (lane == 0) x2s[r] = p;
        }
    }
    __syncthreads();

    const float x2A = x2s[slot];
    const float x2B = x2s[rowB];
    float bestA = 3.402823466e38f, bestB = 3.402823466e38f;
    int biA = 0x7fffffff, biB = 0x7fffffff;

    for (int t = 0; t < NEC / 64; ++t) {
        __syncthreads();
        for (int i = tid; i < KD * 16; i += NTHR) {
            int k = i >> 4, j = i & 15;
            ((float4*)Es)[k * 16 + j] = *(const float4*)(Eg + (size_t)k * NEC + t * 64 + j * 4);
        }
        if (tid < 64) e2s[tid] = e2[t * 64 + tid];
        __syncthreads();

        unsigned long long aA[8], aB[8];
        #pragma unroll
        for (int m = 0; m < 8; ++m) { aA[m] = 0ull; aB[m] = 0ull; }
        #pragma unroll 4
        for (int k = 0; k < KD; ++k) {
            unsigned long long xxA = pack2(Xst[k * PL + slot]);
            unsigned long long xxB = pack2(Xst[k * PL + rowB]);
            const ulonglong2* er = (const ulonglong2*)(Es + k * 64 + qtr * 16);
            #pragma unroll
            for (int j = 0; j < 4; ++j) {
                ulonglong2 e = er[j];
                ffma2(aA[2 * j],     xxA, e.x);
                ffma2(aA[2 * j + 1], xxA, e.y);
                ffma2(aB[2 * j],     xxB, e.x);
                ffma2(aB[2 * j + 1], xxB, e.y);
            }
        }
        #pragma unroll
        for (int m = 0; m < 8; ++m) {
            float eA0 = e2s[qtr * 16 + 2 * m], eA1 = e2s[qtr * 16 + 2 * m + 1];
            int n0 = t * 64 + qtr * 16 + 2 * m;
            float dA0 = __fadd_rn(__fsub_rn(x2A, __fmul_rn(2.f, __uint_as_float((unsigned)aA[m]))), eA0);
            float dA1 = __fadd_rn(__fsub_rn(x2A, __fmul_rn(2.f, __uint_as_float((unsigned)(aA[m] >> 32)))), eA1);
            float dB0 = __fadd_rn(__fsub_rn(x2B, __fmul_rn(2.f, __uint_as_float((unsigned)aB[m]))), eA0);
            float dB1 = __fadd_rn(__fsub_rn(x2B, __fmul_rn(2.f, __uint_as_float((unsigned)(aB[m] >> 32)))), eA1);
            if (dA0 < bestA) { bestA = dA0; biA = n0; }
            if (dA1 < bestA) { bestA = dA1; biA = n0 + 1; }
            if (dB0 < bestB) { bestB = dB0; biB = n0; }
            if (dB1 < bestB) { bestB = dB1; biB = n0 + 1; }
        }
    }
    bv[tid] = bestA; bn[tid] = biA;
    bv[NTHR + tid] = bestB; bn[NTHR + tid] = biB;   // only slots<92 entries are read
    __syncthreads();

    // combine 4 quarters per row: global first-min (smallest index among equal minima)
    if (tid < LL) {
        int base = (tid < QSLOT) ? tid : (NTHR + tid - QSLOT);
        float v = bv[base]; int n = bn[base];
        #pragma unroll
        for (int q = 1; q < 4; ++q) {
            float vq = bv[base + q * QSLOT]; int nq = bn[base + q * QSLOT];
            if (vq < v || (vq == v && nq < n)) { v = vq; n = nq; }
        }
        bestn[tid] = n;
    }
    __syncthreads();

    // gather codes, straight-through q, diff
    float lsum = 0.f;
    for (int idx = tid; idx < LL * KD; idx += NTHR) {
        int ll = idx / KD, d = idx % KD;
        float c  = ET[(size_t)bestn[ll] * KD + d];
        float xv = Xst[d * PL + ll];
        float df = __fsub_rn(c, xv);
        lsum = __fmaf_rn(df, df, lsum);
        qout[((size_t)b * LL + ll) * KD + d] = __fadd_rn(xv, df);
    }
    float bs = block_reduce13(lsum, red);
    if (tid == 0) atomicAdd(acc, (double)bs);
}

// ---- projection + pred + feature loss (unchanged) ----
__global__ __launch_bounds__(NTHR, 1)
void proj_kernel(const float* __restrict__ dec,
                 const float* __restrict__ org,
                 const float* __restrict__ W,
                 const float* __restrict__ bvec,
                 const int*   __restrict__ label,
                 float*       __restrict__ rec_out,
                 float*       __restrict__ pred_out)
{
    constexpr int PL = 197;
    extern __shared__ float sm[];
    float* Dst = sm;                // 128*PL
    float* ps  = Dst + 128 * PL;    // 208
    float* Ws  = ps + 208;          // 128*64
    float* red = Ws + 128 * 64;     // 13

    const int b = blockIdx.x, tid = threadIdx.x;
    const int cb = label[b];
    const int half = (tid >= 208) ? 1 : 0;
    const int l = tid - 208 * half;

    for (int idx = tid; idx < LL * CHN; idx += NTHR) {
        int ll = idx >> 7, d = idx & 127;
        Dst[d * PL + ll] = dec[((size_t)ll * BB + b) * CHN + d];
    }
    const float* Wcb = W + (size_t)cb * CHN * CHN;
    const float* bcb = bvec + cb * CHN;
    float psum = 0.f;

    for (int t = 0; t < 2; ++t) {
        __syncthreads();
        for (int i = tid; i < 128 * 16; i += NTHR) {
            int k = i >> 4, j = i & 15;
            ((float4*)Ws)[k * 16 + j] = *(const float4*)(Wcb + (size_t)k * CHN + t * 64 + j * 4);
        }
        __syncthreads();
        if (l < LL) {
            unsigned long long a2[16];
            #pragma unroll
            for (int j = 0; j < 16; ++j) a2[j] = 0ull;
            #pragma unroll 2
            for (int k = 0; k < 128; ++k) {
                unsigned long long xx = pack2(Dst[k * PL + l]);
                const ulonglong2* er = (const ulonglong2*)(Ws + k * 64 + half * 32);
                #pragma unroll
                for (int j = 0; j < 8; ++j) {
                    ulonglong2 e = er[j];
                    ffma2(a2[2 * j], xx, e.x);
                    ffma2(a2[2 * j + 1], xx, e.y);
                }
            }
            #pragma unroll
            for (int j = 0; j < 16; ++j) {
                #pragma unroll
                for (int s = 0; s < 2; ++s) {
                    float av = __uint_as_float((unsigned)(a2[j] >> (32 * s)));
                    int o = t * 64 + half * 32 + 2 * j + s;
                    float r = __fadd_rn(av, bcb[o]);
                    float g = org[(size_t)b * CHN * LL + (size_t)o * LL + l];
                    float e = __fsub_rn(r, g);
                    psum = __fmaf_rn(e, e, psum);
                    rec_out[(size_t)b * CHN * LL + (size_t)o * LL + l] = r;
                }
            }
        }
    }
    __syncthreads();
    if (half == 1 && l < LL) ps[l] = psum;
    __syncthreads();
    if (half == 0 && l < LL)
        pred_out[(size_t)b * LL + l] = __fsqrt_rn(__fadd_rn(psum, ps[l]));
    float bs = block_reduce13(psum, red);
    if (tid == 0) atomicAdd(&g_acc[5], (double)bs);
}

__global__ void final_k(float* __restrict__ out) {
    if (threadIdx.x == 0 && blockIdx.x == 0) {
        double latent = g_acc[0] / ((double)BB * LL * CC)
                      + (g_acc[1] + g_acc[2] + g_acc[3] + g_acc[4]) / ((double)BB * LL * C2);
        double feat = g_acc[5] / ((double)BB * CHN * LL);
        out[LOSS_OFF + 0] = (float)(0.25 * latent + feat);
        out[LOSS_OFF + 1] = (float)feat;
        out[LOSS_OFF + 2] = (float)latent;
    }
}

extern "C" void kernel_launch(void* const* d_in, const int* in_sizes, int n_in,
                              void* d_out, int out_size) {
    const float* enc      = (const float*)d_in[0];
    const float* dec      = (const float*)d_in[1];
    const float* org      = (const float*)d_in[2];
    const float* embed5   = (const float*)d_in[3];
    const float* embed_hi = (const float*)d_in[4];
    const float* W        = (const float*)d_in[5];
    const float* bvec     = (const float*)d_in[6];
    const int*   label    = (const int*)d_in[7];
    float* out = (float*)d_out;

    // floats: Xst(KD*197) + x2s(196) + Es(KD*64) + e2s(64) + bv(832) + bn(832) + bestn(196) + red(13)
    const size_t sm64  = (size_t)(64  * 197 + 196 + 64  * 64 + 64 + 2 * NTHR + 2 * NTHR + LL + 13 + 16) * 4;
    const size_t sm128 = (size_t)(128 * 197 + 196 + 128 * 64 + 64 + 2 * NTHR + 2 * NTHR + LL + 13 + 16) * 4;
    const size_t smP   = (size_t)(128 * 197 + 208 + 128 * 64 + 13 + 16) * 4;

    cudaFuncSetAttribute(vq_kernel<64, false, 2>, cudaFuncAttributeMaxDynamicSharedMemorySize, (int)sm64);
    cudaFuncSetAttribute(vq_kernel<128, true, 1>, cudaFuncAttributeMaxDynamicSharedMemorySize, (int)sm128);
    cudaFuncSetAttribute(proj_kernel, cudaFuncAttributeMaxDynamicSharedMemorySize, (int)smP);

    // launch order: profiled slot = 0-based launch 3 = vq5
    transpose_k<<<dim3(16, 2, 15), dim3(32, 8)>>>(embed5,   64,  512, 0);   // 0 (zeroes g_acc)
    transpose_k<<<dim3(16, 4, 60), dim3(32, 8)>>>(embed_hi, 128, 512, 1);   // 1
    e2_all_k<<<(75 * 512 + 7) / 8, 256>>>();                                // 2

    vq_kernel<64, false, 2><<<512, NTHR, sm64>>>(                           // 3 <- profiled
        enc + (size_t)4 * BB * LL * CC, embed5, label, nullptr);
    vq_kernel<128, true, 1><<<dim3(512, 4), NTHR, sm128>>>(                 // 4
        enc, embed_hi, label, out + Q_OFF);

    proj_kernel<<<512, NTHR, smP>>>(dec, org, W, bvec, label, out, out + PRED_OFF);  // 5

    final_k<<<1, 1>>>(out);                                                 // 6
}